// round 16
// baseline (speedup 1.0000x reference)
#include <cuda_runtime.h>
#include <cuda_fp16.h>
#include <cstdint>
#include <cstddef>

// Problem constants (fixed shapes)
#define NH   5000
#define NO   15000
#define NN   20000          // NH + NO
#define DD   1024
#define E_HH 20000
#define E_OO 40000
#define E_HO 40000
#define E_TOT 100000

#define FLAG_ACC  1
#define FLAG_RELU 2
#define FLAG_HALF 4

#define YH_TILES 40          // ceil(NH/128)
#define YO_TILES 118         // ceil(NO/128)
#define GEMM_GRID 304        // 2 CTAs/SM x 152 SMs (GB300)

// ---------------- static scratch (no allocations allowed) ----------------
__device__ __half g_u_hh[(size_t)NH * DD];
__device__ __half g_v_hh[(size_t)NH * DD];
__device__ __half g_u_oo[(size_t)NO * DD];
__device__ __half g_v_oo[(size_t)NO * DD];
__device__ __half g_u_ho[(size_t)NH * DD];
__device__ __half g_v_ho[(size_t)NO * DD];
__device__ __half g_nfh[(size_t)NN * DD];           // fp16 n_f (GEMM A + gather source)
__device__ __half g_z  [(size_t)NN * DD];           // fp16 z (GEMM A)
__device__ __half g_wt [(size_t)10 * DD * DD];      // fp16 transposed [N,K] weight halves
__device__ float g_a  [E_TOT];
__device__ int   g_esrc[E_TOT];
__device__ int   g_edst[E_TOT];
__device__ int   g_eidx[E_TOT];
__device__ int   g_deg [NN];
__device__ int   g_off [NN + 1];
__device__ int   g_cur [NN];

// ---------------- small helpers ----------------
__device__ __forceinline__ uint32_t s2u(const void* p) {
    uint32_t a;
    asm("{ .reg .u64 t; cvta.to.shared.u64 t, %1; cvt.u32.u64 %0, t; }" : "=r"(a) : "l"(p));
    return a;
}
__device__ __forceinline__ void cp16(uint32_t dst, const void* src, int sz) {
    asm volatile("cp.async.cg.shared.global [%0], [%1], 16, %2;\n"
                 :: "r"(dst), "l"(src), "r"(sz));
}
__device__ __forceinline__ void ldsm4(uint32_t* r, uint32_t addr) {
    asm volatile("ldmatrix.sync.aligned.m8n8.x4.shared.b16 {%0,%1,%2,%3}, [%4];"
                 : "=r"(r[0]), "=r"(r[1]), "=r"(r[2]), "=r"(r[3]) : "r"(addr));
}
__device__ __forceinline__ void mma_fp16(float* c, const uint32_t* a,
                                         uint32_t b0, uint32_t b1) {
    asm volatile(
        "mma.sync.aligned.m16n8k16.row.col.f32.f16.f16.f32 "
        "{%0,%1,%2,%3}, {%4,%5,%6,%7}, {%8,%9}, {%0,%1,%2,%3};\n"
        : "+f"(c[0]), "+f"(c[1]), "+f"(c[2]), "+f"(c[3])
        : "r"(a[0]), "r"(a[1]), "r"(a[2]), "r"(a[3]), "r"(b0), "r"(b1));
}

// ====== persistent fp16 HMMA GEMM (f32 accumulate), H+O merged ==========
// Tile space: ntiles = xdim * (yH + yO). For tile G: x = G % xdim selects
// {output group wb = x>>3, n-tile n0 = (x&7)*128}; y = G / xdim selects the
// m-tile and side (y < yH -> H, else O). Each CTA processes tiles
// blockIdx.x, +gridDim.x, ... with a CONTINUOUS cp.async pipeline across
// tile boundaries (stages keyed by sequential load index L mod 4); the
// epilogue (regs->global only) overlaps the next tile's in-flight loads.
#define ROWB 80
#define TILE_BYTES (128 * ROWB)        // 10240
#define STG_BYTES (2 * TILE_BYTES)     // 20480 (A + B)
#define NSTAGE 4
#define GEMM_SMEM (NSTAGE * STG_BYTES) // 81920

struct Outs8 { void* c[8]; const float* b[8]; int f[8]; };

__global__ __launch_bounds__(256, 2) void gemm_mma(
    const __half* __restrict__ AH, const __half* __restrict__ AO,
    const __half* __restrict__ BtH, const __half* __restrict__ BtO,
    Outs8 outs, int MH, int MO, int yH, int xdim, int ntiles)
{
    extern __shared__ char smem[];
    const int tid  = threadIdx.x;
    const int lane = tid & 31;
    const int w    = tid >> 5;
    const int wm   = (w >> 2) * 64;
    const int wn   = (w & 3) * 32;
    const int g    = lane >> 2;
    const int tg   = lane & 3;
    const int tr   = lane & 15;
    const int half = lane >> 4;

    const uint32_t sb0 = s2u(smem);
    const int step = gridDim.x;
    if ((int)blockIdx.x >= ntiles) return;
    const int myn = (ntiles - 1 - (int)blockIdx.x) / step + 1;
    const int total = myn * 32;          // sequential k-tile work items

    // fragment LDSM base addresses (stage 0); +half*16 selects k0-7 / k8-15
    uint32_t aaddr[4], baddr[2];
#pragma unroll
    for (int mt = 0; mt < 4; mt++)
        aaddr[mt] = sb0 + (wm + mt * 16 + tr) * ROWB + half * 16;
#pragma unroll
    for (int p = 0; p < 2; p++)
        baddr[p] = sb0 + TILE_BYTES + (wn + p * 16 + tr) * ROWB + half * 16;

    auto issue = [&](int L) {
        const int j  = L >> 5;
        const int kt = L & 31;
        const int G  = (int)blockIdx.x + j * step;
        const int x  = G % xdim;
        const int y  = G / xdim;
        const int wb = x >> 3;
        const int n0 = (x & 7) * 128;
        const int side = (y >= yH) ? 1 : 0;
        const int m0 = (side ? (y - yH) : y) * 128;
        const int M  = side ? MO : MH;
        const __half* Ag = (side ? AO : AH) + (size_t)m0 * 1024 + kt * 32;
        const __half* Bg = (side ? BtO : BtH) + (size_t)wb * 1048576
                           + (size_t)n0 * 1024 + kt * 32;
        const uint32_t s = sb0 + (L & 3) * STG_BYTES;
#pragma unroll
        for (int i = 0; i < 2; i++) {
            int q = tid + i * 256;           // 512 16B chunks (A)
            int r = q >> 2;
            int c = q & 3;
            cp16(s + r * ROWB + c * 16, Ag + (size_t)r * 1024 + c * 8,
                 (m0 + r < M) ? 16 : 0);
        }
#pragma unroll
        for (int i = 0; i < 2; i++) {
            int q = tid + i * 256;           // 512 16B chunks (B)
            int r = q >> 2;
            int c = q & 3;
            cp16(s + TILE_BYTES + r * ROWB + c * 16, Bg + (size_t)r * 1024 + c * 8, 16);
        }
        asm volatile("cp.async.commit_group;\n");
    };

    float acc[4][4][4];
#pragma unroll
    for (int mt = 0; mt < 4; mt++)
#pragma unroll
        for (int nt = 0; nt < 4; nt++)
#pragma unroll
            for (int r = 0; r < 4; r++) acc[mt][nt][r] = 0.f;

    int li = 0;
    for (; li < 3 && li < total; li++) issue(li);

#pragma unroll 1
    for (int C = 0; C < total; C++) {
        const int rem = li - C - 1;       // groups allowed to stay pending
        if (rem >= 2)      asm volatile("cp.async.wait_group 2;\n");
        else if (rem == 1) asm volatile("cp.async.wait_group 1;\n");
        else               asm volatile("cp.async.wait_group 0;\n");
        __syncthreads();
        // all warps finished compute of C-1 at this barrier, so issuing
        // load C+3 (stage (C-1)&3) is safe
        if (li < total) { issue(li); li++; }

        const uint32_t bo = (C & 3) * STG_BYTES;
#pragma unroll
        for (int s16 = 0; s16 < 2; s16++) {
            const uint32_t ko = bo + s16 * 32;
            uint32_t af[4][4], bf[2][4];
#pragma unroll
            for (int mt = 0; mt < 4; mt++)
                ldsm4(af[mt], aaddr[mt] + ko);
#pragma unroll
            for (int p = 0; p < 2; p++)
                ldsm4(bf[p], baddr[p] + ko);
#pragma unroll
            for (int mt = 0; mt < 4; mt++) {
#pragma unroll
                for (int nt = 0; nt < 4; nt++) {
                    int p = nt >> 1, o = nt & 1;
                    mma_fp16(acc[mt][nt], af[mt], bf[p][o], bf[p][o + 2]);
                }
            }
        }

        if ((C & 31) == 31) {
            // epilogue for tile j = C>>5 (next tile's loads already in flight;
            // this path touches registers + global only, never SMEM)
            const int G  = (int)blockIdx.x + (C >> 5) * step;
            const int x  = G % xdim;
            const int y  = G / xdim;
            const int wb = x >> 3;
            const int n0 = (x & 7) * 128;
            const int side = (y >= yH) ? 1 : 0;
            const int m0 = (side ? (y - yH) : y) * 128;
            const int M  = side ? MO : MH;
            const int oidx = wb + side * 4;
            const int flags = outs.f[oidx];
            const float* bias = outs.b[oidx];
            float* Cf = (float*)outs.c[oidx];
            __half* Ch = (__half*)outs.c[oidx];
#pragma unroll
            for (int mt = 0; mt < 4; mt++) {
#pragma unroll
                for (int part = 0; part < 2; part++) {
                    int rr = m0 + wm + mt * 16 + g + part * 8;
                    if (rr >= M) continue;
#pragma unroll
                    for (int nt = 0; nt < 4; nt++) {
                        int cc = wn + nt * 8 + 2 * tg;
                        float vx = acc[mt][nt][part * 2 + 0];
                        float vy = acc[mt][nt][part * 2 + 1];
                        if (flags & FLAG_ACC) {
                            float2 c = *(const float2*)(Cf + (size_t)rr * 1024 + n0 + cc);
                            vx += c.x; vy += c.y;
                        }
                        if (bias) {
                            vx += bias[n0 + cc];
                            vy += bias[n0 + cc + 1];
                        }
                        if (flags & FLAG_RELU) {
                            vx = fmaxf(vx, 0.f);
                            vy = fmaxf(vy, 0.f);
                        }
                        if (flags & FLAG_HALF) {
                            *(__half2*)(Ch + (size_t)rr * 1024 + n0 + cc) =
                                __floats2half2_rn(vx, vy);
                        } else {
                            *(float2*)(Cf + (size_t)rr * 1024 + n0 + cc) =
                                make_float2(vx, vy);
                        }
                    }
                }
            }
#pragma unroll
            for (int mt = 0; mt < 4; mt++)
#pragma unroll
                for (int nt = 0; nt < 4; nt++)
#pragma unroll
                    for (int r = 0; r < 4; r++) acc[mt][nt][r] = 0.f;
        }
    }
}

// ---------------- fp32 -> fp16 convert ----------------
__global__ void to_half_kernel(const float* __restrict__ src,
                               __half* __restrict__ dst, int n4)
{
    int i = blockIdx.x * blockDim.x + threadIdx.x;
    if (i >= n4) return;
    float4 v = ((const float4*)src)[i];
    ((__half2*)dst)[i * 2 + 0] = __floats2half2_rn(v.x, v.y);
    ((__half2*)dst)[i * 2 + 1] = __floats2half2_rn(v.z, v.w);
}

// batched: dst_i[n*1024+k] = (half)src_i[k*1024+n], i = blockIdx.z
struct TP10 { const float* s[10]; };
__global__ void transpose_half10_kernel(TP10 tp, __half* __restrict__ dstbase)
{
    __shared__ float t[32][33];
    const float* src = tp.s[blockIdx.z];
    __half* dst = dstbase + (size_t)blockIdx.z * DD * DD;
    int bx = blockIdx.x * 32, by = blockIdx.y * 32;
#pragma unroll
    for (int i = threadIdx.y; i < 32; i += 8)
        t[i][threadIdx.x] = src[(size_t)(by + i) * 1024 + bx + threadIdx.x];
    __syncthreads();
#pragma unroll
    for (int i = threadIdx.y; i < 32; i += 8)
        dst[(size_t)(bx + i) * 1024 + by + threadIdx.x] =
            __float2half_rn(t[threadIdx.x][i]);
}

// ---------------- edge bookkeeping (fused) ----------------
__global__ void build_edges_hist_kernel(
    const int* __restrict__ shh, const int* __restrict__ dhh,
    const int* __restrict__ soo, const int* __restrict__ doo,
    const int* __restrict__ sho, const int* __restrict__ dho)
{
    int e = blockIdx.x * blockDim.x + threadIdx.x;
    if (e >= E_TOT) return;
    int s, d;
    if (e < E_HH)               { s = shh[e];             d = dhh[e]; }
    else if (e < E_HH + E_OO)   { s = soo[e - E_HH];      d = doo[e - E_HH]; }
    else                        { s = sho[e - E_HH - E_OO]; d = dho[e - E_HH - E_OO]; }
    g_esrc[e] = s;
    g_edst[e] = d;
    atomicAdd(&g_deg[d], 1);
}

// coalesced multi-round block scan
__global__ __launch_bounds__(1024) void scan_deg_kernel()
{
    __shared__ int wsum[32];
    int tid = threadIdx.x;
    int lane = tid & 31, wid = tid >> 5;
    int carry = 0;
    if (tid == 0) g_off[0] = 0;
    for (int base = 0; base < NN; base += 1024) {
        int i = base + tid;
        int v = (i < NN) ? g_deg[i] : 0;
        int inc = v;
#pragma unroll
        for (int o = 1; o < 32; o <<= 1) {
            int t = __shfl_up_sync(0xffffffffu, inc, o);
            if (lane >= o) inc += t;
        }
        if (lane == 31) wsum[wid] = inc;
        __syncthreads();
        if (wid == 0) {
            int s = wsum[lane];
#pragma unroll
            for (int o = 1; o < 32; o <<= 1) {
                int t = __shfl_up_sync(0xffffffffu, s, o);
                if (lane >= o) s += t;
            }
            wsum[lane] = s;
        }
        __syncthreads();
        int excl = inc - v + (wid ? wsum[wid - 1] : 0) + carry;
        if (i < NN) {
            g_cur[i] = excl;
            g_off[i + 1] = excl + v;
        }
        carry += wsum[31];
        __syncthreads();
    }
}

__global__ void scatter_kernel()
{
    int e = blockIdx.x * blockDim.x + threadIdx.x;
    if (e >= E_TOT) return;
    int p = atomicAdd(&g_cur[g_edst[e]], 1);
    g_eidx[p] = e;
}

// ---------------- attention logits: a[e] = relu(u+v) . W_att + b --------
__global__ void edge_logits_kernel(const float* __restrict__ W_att,
                                   const float* __restrict__ b_att)
{
    int gw = (blockIdx.x * blockDim.x + threadIdx.x) >> 5;
    int lane = threadIdx.x & 31;
    if (gw >= E_TOT) return;
    int e = gw;
    int src = g_esrc[e], dst = g_edst[e];
    const __half *u, *v;
    if (e < E_HH) {
        u = g_u_hh + (size_t)src * DD;
        v = g_v_hh + (size_t)dst * DD;
    } else if (e < E_HH + E_OO) {
        u = g_u_oo + (size_t)(src - NH) * DD;
        v = g_v_oo + (size_t)(dst - NH) * DD;
    } else {
        u = g_u_ho + (size_t)src * DD;
        v = g_v_ho + (size_t)(dst - NH) * DD;
    }
    float sum = 0.f;
#pragma unroll
    for (int it = 0; it < 4; it++) {
        int d = it * 256 + lane * 8;
        uint4 ur = *(const uint4*)(u + d);
        uint4 vr = *(const uint4*)(v + d);
        float4 w0 = *(const float4*)(W_att + d);
        float4 w1 = *(const float4*)(W_att + d + 4);
        const uint32_t* up = &ur.x;
        const uint32_t* vp = &vr.x;
        float ws[8] = {w0.x, w0.y, w0.z, w0.w, w1.x, w1.y, w1.z, w1.w};
#pragma unroll
        for (int j = 0; j < 4; j++) {
            float2 uf = __half22float2(*(const __half2*)&up[j]);
            float2 vf = __half22float2(*(const __half2*)&vp[j]);
            sum += fmaxf(uf.x + vf.x, 0.f) * ws[j * 2 + 0]
                 + fmaxf(uf.y + vf.y, 0.f) * ws[j * 2 + 1];
        }
    }
#pragma unroll
    for (int o = 16; o > 0; o >>= 1)
        sum += __shfl_xor_sync(0xffffffffu, sum, o);
    if (lane == 0) g_a[e] = sum + b_att[0];
}

// ---------------- per-dst softmax + weighted aggregation into z ----------
__global__ __launch_bounds__(128) void softmax_z_kernel()
{
    int n = blockIdx.x;
    int tid = threadIdx.x;
    int s0 = g_off[n], s1 = g_off[n + 1];
    __half* zrow = g_z + (size_t)n * DD;

    if (s1 == s0) {
        __half2 zh = __floats2half2_rn(0.f, 0.f);
#pragma unroll
        for (int j = 0; j < 4; j++)
            ((__half2*)zrow)[tid * 4 + j] = zh;
        return;
    }

    __shared__ float red[128];

    float m = -1e30f;
    for (int i = s0 + tid; i < s1; i += 128)
        m = fmaxf(m, g_a[g_eidx[i]]);
    red[tid] = m;
    __syncthreads();
    for (int s = 64; s > 0; s >>= 1) {
        if (tid < s) red[tid] = fmaxf(red[tid], red[tid + s]);
        __syncthreads();
    }
    float mx = red[0];
    __syncthreads();

    float se = 0.f;
    for (int i = s0 + tid; i < s1; i += 128)
        se += expf(g_a[g_eidx[i]] - mx);
    red[tid] = se;
    __syncthreads();
    for (int s = 64; s > 0; s >>= 1) {
        if (tid < s) red[tid] += red[tid + s];
        __syncthreads();
    }
    float inv = 1.f / red[0];

    float acc[8];
#pragma unroll
    for (int j = 0; j < 8; j++) acc[j] = 0.f;

    for (int i = s0; i < s1; i++) {
        int e = g_eidx[i];
        float wgt = expf(g_a[e] - mx) * inv;
        const __half* row = g_nfh + (size_t)g_esrc[e] * DD;
        uint4 raw = *(const uint4*)(row + tid * 8);
        const uint32_t* rp = &raw.x;
#pragma unroll
        for (int j = 0; j < 4; j++) {
            float2 f = __half22float2(*(const __half2*)&rp[j]);
            acc[j * 2 + 0] += wgt * f.x;
            acc[j * 2 + 1] += wgt * f.y;
        }
    }
#pragma unroll
    for (int j = 0; j < 4; j++)
        ((__half2*)zrow)[tid * 4 + j] = __floats2half2_rn(acc[j * 2], acc[j * 2 + 1]);
}

// ---------------- launch ----------------
extern "C" void kernel_launch(void* const* d_in, const int* in_sizes, int n_in,
                              void* d_out, int out_size)
{
    const float* n_f    = (const float*)d_in[0];
    const int*   src_hh = (const int*)d_in[1];
    const int*   dst_hh = (const int*)d_in[2];
    const int*   src_oo = (const int*)d_in[3];
    const int*   dst_oo = (const int*)d_in[4];
    const int*   src_ho = (const int*)d_in[5];
    const int*   dst_ho = (const int*)d_in[6];
    const float* W_hh   = (const float*)d_in[7];
    const float* b_hh   = (const float*)d_in[8];
    const float* W_oo   = (const float*)d_in[9];
    const float* b_oo   = (const float*)d_in[10];
    const float* W_ho   = (const float*)d_in[11];
    const float* b_ho   = (const float*)d_in[12];
    const float* W_att  = (const float*)d_in[13];
    const float* b_att  = (const float*)d_in[14];
    const float* W_hn   = (const float*)d_in[15];
    const float* b_hn   = (const float*)d_in[16];
    const float* W_on   = (const float*)d_in[17];
    const float* b_on   = (const float*)d_in[18];
    float* out = (float*)d_out;

    void* p;
    __half *u_hh, *v_hh, *u_oo, *v_oo, *u_ho, *v_ho, *nfh, *z, *wt;
    int* deg;
    cudaGetSymbolAddress(&p, g_u_hh); u_hh = (__half*)p;
    cudaGetSymbolAddress(&p, g_v_hh); v_hh = (__half*)p;
    cudaGetSymbolAddress(&p, g_u_oo); u_oo = (__half*)p;
    cudaGetSymbolAddress(&p, g_v_oo); v_oo = (__half*)p;
    cudaGetSymbolAddress(&p, g_u_ho); u_ho = (__half*)p;
    cudaGetSymbolAddress(&p, g_v_ho); v_ho = (__half*)p;
    cudaGetSymbolAddress(&p, g_nfh);  nfh  = (__half*)p;
    cudaGetSymbolAddress(&p, g_z);    z    = (__half*)p;
    cudaGetSymbolAddress(&p, g_wt);   wt   = (__half*)p;
    cudaGetSymbolAddress(&p, g_deg);  deg  = (int*)p;

    cudaFuncSetAttribute(gemm_mma,
                         cudaFuncAttributeMaxDynamicSharedMemorySize, GEMM_SMEM);

    const size_t WOFF = (size_t)DD * DD;   // bottom half of [2D,D] weight
    const size_t MSZ  = (size_t)DD * DD;
    dim3 thr(256);

    // ---- fp16 operand prep + CSR bookkeeping ----
    cudaMemsetAsync(deg, 0, NN * sizeof(int));
    to_half_kernel<<<((NN * DD / 4) + 255) / 256, 256>>>(n_f, nfh, NN * DD / 4);
    {
        TP10 tp;
        tp.s[0] = W_hh;        tp.s[1] = W_hh + WOFF;
        tp.s[2] = W_ho;        tp.s[3] = W_hn;
        tp.s[4] = W_oo;        tp.s[5] = W_oo + WOFF;
        tp.s[6] = W_ho + WOFF; tp.s[7] = W_on;
        tp.s[8] = W_hn + WOFF; tp.s[9] = W_on + WOFF;
        transpose_half10_kernel<<<dim3(32, 32, 10), dim3(32, 8)>>>(tp, wt);
    }
    build_edges_hist_kernel<<<(E_TOT + 255) / 256, 256>>>(src_hh, dst_hh, src_oo, dst_oo, src_ho, dst_ho);
    scan_deg_kernel<<<1, 1024>>>();
    scatter_kernel<<<(E_TOT + 255) / 256, 256>>>();

    const __half* nfhH = nfh;
    const __half* nfhO = nfh + (size_t)NH * DD;
    float* outH = out;
    float* outO = out + (size_t)NH * DD;

    // merged first-phase GEMMs: all 8 outputs, persistent grid
    {
        Outs8 o;
        o.c[0] = u_hh; o.c[1] = v_hh; o.c[2] = u_ho; o.c[3] = outH;
        o.c[4] = u_oo; o.c[5] = v_oo; o.c[6] = v_ho; o.c[7] = outO;
        o.b[0] = nullptr; o.b[1] = b_hh; o.b[2] = nullptr; o.b[3] = nullptr;
        o.b[4] = nullptr; o.b[5] = b_oo; o.b[6] = b_ho;    o.b[7] = nullptr;
        o.f[0] = FLAG_HALF; o.f[1] = FLAG_HALF; o.f[2] = FLAG_HALF; o.f[3] = 0;
        o.f[4] = FLAG_HALF; o.f[5] = FLAG_HALF; o.f[6] = FLAG_HALF; o.f[7] = 0;
        const int ntiles = 32 * (YH_TILES + YO_TILES);   // 5056
        gemm_mma<<<GEMM_GRID, thr, GEMM_SMEM>>>(
            nfhH, nfhO, wt, wt + 4 * MSZ, o, NH, NO, YH_TILES, 32, ntiles);
    }

    // attention logits + softmax-weighted aggregation
    edge_logits_kernel<<<(E_TOT * 32 + 255) / 256, 256>>>(W_att, b_att);
    softmax_z_kernel<<<NN, 128>>>();

    // merged z-phase GEMMs: persistent grid
    {
        Outs8 o;
        o.c[0] = outH; o.b[0] = b_hn; o.f[0] = FLAG_ACC | FLAG_RELU;
        o.c[4] = outO; o.b[4] = b_on; o.f[4] = FLAG_ACC | FLAG_RELU;
        o.c[1] = o.c[2] = o.c[3] = o.c[5] = o.c[6] = o.c[7] = nullptr;
        o.b[1] = o.b[2] = o.b[3] = o.b[5] = o.b[6] = o.b[7] = nullptr;
        o.f[1] = o.f[2] = o.f[3] = o.f[5] = o.f[6] = o.f[7] = 0;
        const int ntiles = 8 * (YH_TILES + YO_TILES);    // 1264
        gemm_mma<<<GEMM_GRID, thr, GEMM_SMEM>>>(
            z, z + (size_t)NH * DD, wt + 8 * MSZ, wt + 9 * MSZ, o, NH, NO, YH_TILES, 8, ntiles);
    }
}

// round 17
// speedup vs baseline: 1.0896x; 1.0896x over previous
#include <cuda_runtime.h>
#include <cuda_fp16.h>
#include <cstdint>
#include <cstddef>

// Problem constants (fixed shapes)
#define NH   5000
#define NO   15000
#define NN   20000          // NH + NO
#define DD   1024
#define E_HH 20000
#define E_OO 40000
#define E_HO 40000
#define E_TOT 100000

#define FLAG_ACC  1
#define FLAG_RELU 2
#define FLAG_HALF 4

#define YH_TILES 40          // ceil(NH/128)
#define YO_TILES 118         // ceil(NO/128)

// ---------------- static scratch (no allocations allowed) ----------------
__device__ __half g_u_hh[(size_t)NH * DD];
__device__ __half g_v_hh[(size_t)NH * DD];
__device__ __half g_u_oo[(size_t)NO * DD];
__device__ __half g_v_oo[(size_t)NO * DD];
__device__ __half g_u_ho[(size_t)NH * DD];
__device__ __half g_v_ho[(size_t)NO * DD];
__device__ __half g_nfh[(size_t)NN * DD];           // fp16 n_f (GEMM A + gather source)
__device__ __half g_z  [(size_t)NN * DD];           // fp16 z (GEMM A)
__device__ __half g_wt [(size_t)10 * DD * DD];      // fp16 transposed [N,K] weight halves
__device__ float g_a  [E_TOT];
__device__ int   g_esrc[E_TOT];
__device__ int   g_edst[E_TOT];
__device__ int   g_eidx[E_TOT];
__device__ int   g_deg [NN];
__device__ int   g_off [NN + 1];
__device__ int   g_cur [NN];

// ---------------- small helpers ----------------
__device__ __forceinline__ uint32_t s2u(const void* p) {
    uint32_t a;
    asm("{ .reg .u64 t; cvta.to.shared.u64 t, %1; cvt.u32.u64 %0, t; }" : "=r"(a) : "l"(p));
    return a;
}
__device__ __forceinline__ void cp16(uint32_t dst, const void* src, int sz) {
    asm volatile("cp.async.cg.shared.global [%0], [%1], 16, %2;\n"
                 :: "r"(dst), "l"(src), "r"(sz));
}
__device__ __forceinline__ void ldsm4(uint32_t* r, uint32_t addr) {
    asm volatile("ldmatrix.sync.aligned.m8n8.x4.shared.b16 {%0,%1,%2,%3}, [%4];"
                 : "=r"(r[0]), "=r"(r[1]), "=r"(r[2]), "=r"(r[3]) : "r"(addr));
}
__device__ __forceinline__ void mma_fp16(float* c, const uint32_t* a,
                                         uint32_t b0, uint32_t b1) {
    asm volatile(
        "mma.sync.aligned.m16n8k16.row.col.f32.f16.f16.f32 "
        "{%0,%1,%2,%3}, {%4,%5,%6,%7}, {%8,%9}, {%0,%1,%2,%3};\n"
        : "+f"(c[0]), "+f"(c[1]), "+f"(c[2]), "+f"(c[3])
        : "r"(a[0]), "r"(a[1]), "r"(a[2]), "r"(a[3]), "r"(b0), "r"(b1));
}

// ================= fp16 HMMA GEMM (f32 accumulate), H+O merged ==========
// blockIdx.y < yH  -> H side: A=AH, M=MH, weights BtH, outputs idx wb
// blockIdx.y >= yH -> O side: A=AO, M=MO, weights BtO, outputs idx wb+4
// wb = blockIdx.x>>3 selects output group; (blockIdx.x&7) is the n-tile.
// CTA tile 128x128, 8 warps (2x4), warp 64x32, 4x4 m16n8k16.
// 4-stage cp.async pipeline, wait_group 2.
#define ROWB 80
#define TILE_BYTES (128 * ROWB)        // 10240
#define STG_BYTES (2 * TILE_BYTES)     // 20480 (A + B)
#define NSTAGE 4
#define GEMM_SMEM (NSTAGE * STG_BYTES) // 81920

struct Outs8 { void* c[8]; const float* b[8]; int f[8]; };

__global__ __launch_bounds__(256, 2) void gemm_mma(
    const __half* __restrict__ AH, const __half* __restrict__ AO,
    const __half* __restrict__ BtH, const __half* __restrict__ BtO,
    Outs8 outs, int MH, int MO, int yH)
{
    extern __shared__ char smem[];
    const int tid  = threadIdx.x;
    const int lane = tid & 31;
    const int w    = tid >> 5;
    const int wm   = (w >> 2) * 64;
    const int wn   = (w & 3) * 32;
    const int g    = lane >> 2;
    const int tg   = lane & 3;
    const int tr   = lane & 15;
    const int half = lane >> 4;

    const int wb = blockIdx.x >> 3;
    const int n0 = (blockIdx.x & 7) * 128;

    const int side = (blockIdx.y >= yH) ? 1 : 0;
    const int m0 = (side ? (blockIdx.y - yH) : blockIdx.y) * 128;
    const int M = side ? MO : MH;
    const int oidx = wb + side * 4;

    const uint32_t sb0 = s2u(smem);
    const __half* Bg0 = (side ? BtO : BtH) + (size_t)wb * 1048576 + (size_t)n0 * 1024;
    const __half* Ag0 = (side ? AO : AH) + (size_t)m0 * 1024;

    float acc[4][4][4];
#pragma unroll
    for (int mt = 0; mt < 4; mt++)
#pragma unroll
        for (int nt = 0; nt < 4; nt++)
#pragma unroll
            for (int r = 0; r < 4; r++) acc[mt][nt][r] = 0.f;

    uint32_t aaddr[4], baddr[2];
#pragma unroll
    for (int mt = 0; mt < 4; mt++)
        aaddr[mt] = sb0 + (wm + mt * 16 + tr) * ROWB + half * 16;
#pragma unroll
    for (int p = 0; p < 2; p++)
        baddr[p] = sb0 + TILE_BYTES + (wn + p * 16 + tr) * ROWB + half * 16;

    auto load = [&](int kt) {
        uint32_t s = sb0 + (kt % NSTAGE) * STG_BYTES;
        const __half* Ag = Ag0 + kt * 32;
        const __half* Bg = Bg0 + kt * 32;
#pragma unroll
        for (int i = 0; i < 2; i++) {
            int q = tid + i * 256;           // 512 16B chunks (A)
            int r = q >> 2;
            int c = q & 3;
            cp16(s + r * ROWB + c * 16, Ag + (size_t)r * 1024 + c * 8,
                 (m0 + r < M) ? 16 : 0);
        }
#pragma unroll
        for (int i = 0; i < 2; i++) {
            int q = tid + i * 256;           // 512 16B chunks (B)
            int r = q >> 2;
            int c = q & 3;
            cp16(s + TILE_BYTES + r * ROWB + c * 16, Bg + (size_t)r * 1024 + c * 8, 16);
        }
        asm volatile("cp.async.commit_group;\n");
    };

    const int NT = 32;
    load(0);
    load(1);
    load(2);

    for (int kt = 0; kt < NT; kt++) {
        if (kt < NT - 2)       asm volatile("cp.async.wait_group 2;\n");
        else if (kt == NT - 2) asm volatile("cp.async.wait_group 1;\n");
        else                   asm volatile("cp.async.wait_group 0;\n");
        __syncthreads();
        if (kt + 3 < NT) load(kt + 3);

        const uint32_t bo = (kt % NSTAGE) * STG_BYTES;
#pragma unroll
        for (int s16 = 0; s16 < 2; s16++) {
            const uint32_t ko = bo + s16 * 32;
            uint32_t af[4][4], bf[2][4];
#pragma unroll
            for (int mt = 0; mt < 4; mt++)
                ldsm4(af[mt], aaddr[mt] + ko);
#pragma unroll
            for (int p = 0; p < 2; p++)
                ldsm4(bf[p], baddr[p] + ko);
#pragma unroll
            for (int mt = 0; mt < 4; mt++) {
#pragma unroll
                for (int nt = 0; nt < 4; nt++) {
                    int p = nt >> 1, o = nt & 1;
                    mma_fp16(acc[mt][nt], af[mt], bf[p][o], bf[p][o + 2]);
                }
            }
        }
    }

    // epilogue
    const int flags = outs.f[oidx];
    const float* bias = outs.b[oidx];
    float* Cf = (float*)outs.c[oidx];
    __half* Ch = (__half*)outs.c[oidx];
#pragma unroll
    for (int mt = 0; mt < 4; mt++) {
#pragma unroll
        for (int part = 0; part < 2; part++) {
            int rr = m0 + wm + mt * 16 + g + part * 8;
            if (rr >= M) continue;
#pragma unroll
            for (int nt = 0; nt < 4; nt++) {
                int cc = wn + nt * 8 + 2 * tg;
                float vx = acc[mt][nt][part * 2 + 0];
                float vy = acc[mt][nt][part * 2 + 1];
                if (flags & FLAG_ACC) {
                    float2 c = *(const float2*)(Cf + (size_t)rr * 1024 + n0 + cc);
                    vx += c.x; vy += c.y;
                }
                if (bias) {
                    vx += bias[n0 + cc];
                    vy += bias[n0 + cc + 1];
                }
                if (flags & FLAG_RELU) {
                    vx = fmaxf(vx, 0.f);
                    vy = fmaxf(vy, 0.f);
                }
                if (flags & FLAG_HALF) {
                    *(__half2*)(Ch + (size_t)rr * 1024 + n0 + cc) =
                        __floats2half2_rn(vx, vy);
                } else {
                    *(float2*)(Cf + (size_t)rr * 1024 + n0 + cc) =
                        make_float2(vx, vy);
                }
            }
        }
    }
}

// ---------------- fp32 -> fp16 convert ----------------
__global__ void to_half_kernel(const float* __restrict__ src,
                               __half* __restrict__ dst, int n4)
{
    int i = blockIdx.x * blockDim.x + threadIdx.x;
    if (i >= n4) return;
    float4 v = ((const float4*)src)[i];
    ((__half2*)dst)[i * 2 + 0] = __floats2half2_rn(v.x, v.y);
    ((__half2*)dst)[i * 2 + 1] = __floats2half2_rn(v.z, v.w);
}

// batched: dst_i[n*1024+k] = (half)src_i[k*1024+n], i = blockIdx.z
struct TP10 { const float* s[10]; };
__global__ void transpose_half10_kernel(TP10 tp, __half* __restrict__ dstbase)
{
    __shared__ float t[32][33];
    const float* src = tp.s[blockIdx.z];
    __half* dst = dstbase + (size_t)blockIdx.z * DD * DD;
    int bx = blockIdx.x * 32, by = blockIdx.y * 32;
#pragma unroll
    for (int i = threadIdx.y; i < 32; i += 8)
        t[i][threadIdx.x] = src[(size_t)(by + i) * 1024 + bx + threadIdx.x];
    __syncthreads();
#pragma unroll
    for (int i = threadIdx.y; i < 32; i += 8)
        dst[(size_t)(bx + i) * 1024 + by + threadIdx.x] =
            __float2half_rn(t[threadIdx.x][i]);
}

// ---------------- edge bookkeeping (fused) ----------------
__global__ void build_edges_hist_kernel(
    const int* __restrict__ shh, const int* __restrict__ dhh,
    const int* __restrict__ soo, const int* __restrict__ doo,
    const int* __restrict__ sho, const int* __restrict__ dho)
{
    int e = blockIdx.x * blockDim.x + threadIdx.x;
    if (e >= E_TOT) return;
    int s, d;
    if (e < E_HH)               { s = shh[e];             d = dhh[e]; }
    else if (e < E_HH + E_OO)   { s = soo[e - E_HH];      d = doo[e - E_HH]; }
    else                        { s = sho[e - E_HH - E_OO]; d = dho[e - E_HH - E_OO]; }
    g_esrc[e] = s;
    g_edst[e] = d;
    atomicAdd(&g_deg[d], 1);
}

// block scan: preload all 20 rounds coalesced (MLP=20, one latency), then
// shuffle-scan per round from registers.
#define SCAN_R 20            // 20 * 1024 >= NN
__global__ __launch_bounds__(1024) void scan_deg_kernel()
{
    __shared__ int wsum[32];
    int tid = threadIdx.x;
    int lane = tid & 31, wid = tid >> 5;
    int vals[SCAN_R];
#pragma unroll
    for (int j = 0; j < SCAN_R; j++) {
        int i = j * 1024 + tid;
        vals[j] = (i < NN) ? g_deg[i] : 0;
    }
    int carry = 0;
    if (tid == 0) g_off[0] = 0;
#pragma unroll
    for (int j = 0; j < SCAN_R; j++) {
        int v = vals[j];
        int inc = v;
#pragma unroll
        for (int o = 1; o < 32; o <<= 1) {
            int t = __shfl_up_sync(0xffffffffu, inc, o);
            if (lane >= o) inc += t;
        }
        if (lane == 31) wsum[wid] = inc;
        __syncthreads();
        if (wid == 0) {
            int s = wsum[lane];
#pragma unroll
            for (int o = 1; o < 32; o <<= 1) {
                int t = __shfl_up_sync(0xffffffffu, s, o);
                if (lane >= o) s += t;
            }
            wsum[lane] = s;
        }
        __syncthreads();
        int excl = inc - v + (wid ? wsum[wid - 1] : 0) + carry;
        int i = j * 1024 + tid;
        if (i < NN) {
            g_cur[i] = excl;
            g_off[i + 1] = excl + v;
        }
        carry += wsum[31];
        __syncthreads();   // protect wsum before next round overwrites
    }
}

__global__ void scatter_kernel()
{
    int e = blockIdx.x * blockDim.x + threadIdx.x;
    if (e >= E_TOT) return;
    int p = atomicAdd(&g_cur[g_edst[e]], 1);
    g_eidx[p] = e;
}

// ---------------- attention logits in CSR order ----------------
// warp i handles edge g_eidx[i]; consecutive warps share the same dst,
// so the v-row hits L1/L2 instead of being refetched per edge.
__global__ void edge_logits_kernel(const float* __restrict__ W_att,
                                   const float* __restrict__ b_att)
{
    int gw = (blockIdx.x * blockDim.x + threadIdx.x) >> 5;
    int lane = threadIdx.x & 31;
    if (gw >= E_TOT) return;
    int e = g_eidx[gw];
    int src = g_esrc[e], dst = g_edst[e];
    const __half *u, *v;
    if (e < E_HH) {
        u = g_u_hh + (size_t)src * DD;
        v = g_v_hh + (size_t)dst * DD;
    } else if (e < E_HH + E_OO) {
        u = g_u_oo + (size_t)(src - NH) * DD;
        v = g_v_oo + (size_t)(dst - NH) * DD;
    } else {
        u = g_u_ho + (size_t)src * DD;
        v = g_v_ho + (size_t)(dst - NH) * DD;
    }
    float sum = 0.f;
#pragma unroll
    for (int it = 0; it < 4; it++) {
        int d = it * 256 + lane * 8;
        uint4 ur = *(const uint4*)(u + d);
        uint4 vr = *(const uint4*)(v + d);
        float4 w0 = *(const float4*)(W_att + d);
        float4 w1 = *(const float4*)(W_att + d + 4);
        const uint32_t* up = &ur.x;
        const uint32_t* vp = &vr.x;
        float ws[8] = {w0.x, w0.y, w0.z, w0.w, w1.x, w1.y, w1.z, w1.w};
#pragma unroll
        for (int j = 0; j < 4; j++) {
            float2 uf = __half22float2(*(const __half2*)&up[j]);
            float2 vf = __half22float2(*(const __half2*)&vp[j]);
            sum += fmaxf(uf.x + vf.x, 0.f) * ws[j * 2 + 0]
                 + fmaxf(uf.y + vf.y, 0.f) * ws[j * 2 + 1];
        }
    }
#pragma unroll
    for (int o = 16; o > 0; o >>= 1)
        sum += __shfl_xor_sync(0xffffffffu, sum, o);
    if (lane == 0) g_a[e] = sum + b_att[0];
}

// ---------------- per-dst softmax + weighted aggregation into z ----------
__global__ __launch_bounds__(128) void softmax_z_kernel()
{
    int n = blockIdx.x;
    int tid = threadIdx.x;
    int s0 = g_off[n], s1 = g_off[n + 1];
    __half* zrow = g_z + (size_t)n * DD;

    if (s1 == s0) {
        __half2 zh = __floats2half2_rn(0.f, 0.f);
#pragma unroll
        for (int j = 0; j < 4; j++)
            ((__half2*)zrow)[tid * 4 + j] = zh;
        return;
    }

    __shared__ float red[128];

    float m = -1e30f;
    for (int i = s0 + tid; i < s1; i += 128)
        m = fmaxf(m, g_a[g_eidx[i]]);
    red[tid] = m;
    __syncthreads();
    for (int s = 64; s > 0; s >>= 1) {
        if (tid < s) red[tid] = fmaxf(red[tid], red[tid + s]);
        __syncthreads();
    }
    float mx = red[0];
    __syncthreads();

    float se = 0.f;
    for (int i = s0 + tid; i < s1; i += 128)
        se += expf(g_a[g_eidx[i]] - mx);
    red[tid] = se;
    __syncthreads();
    for (int s = 64; s > 0; s >>= 1) {
        if (tid < s) red[tid] += red[tid + s];
        __syncthreads();
    }
    float inv = 1.f / red[0];

    float acc[8];
#pragma unroll
    for (int j = 0; j < 8; j++) acc[j] = 0.f;

    for (int i = s0; i < s1; i++) {
        int e = g_eidx[i];
        float wgt = expf(g_a[e] - mx) * inv;
        const __half* row = g_nfh + (size_t)g_esrc[e] * DD;
        uint4 raw = *(const uint4*)(row + tid * 8);
        const uint32_t* rp = &raw.x;
#pragma unroll
        for (int j = 0; j < 4; j++) {
            float2 f = __half22float2(*(const __half2*)&rp[j]);
            acc[j * 2 + 0] += wgt * f.x;
            acc[j * 2 + 1] += wgt * f.y;
        }
    }
#pragma unroll
    for (int j = 0; j < 4; j++)
        ((__half2*)zrow)[tid * 4 + j] = __floats2half2_rn(acc[j * 2], acc[j * 2 + 1]);
}

// ---------------- launch ----------------
extern "C" void kernel_launch(void* const* d_in, const int* in_sizes, int n_in,
                              void* d_out, int out_size)
{
    const float* n_f    = (const float*)d_in[0];
    const int*   src_hh = (const int*)d_in[1];
    const int*   dst_hh = (const int*)d_in[2];
    const int*   src_oo = (const int*)d_in[3];
    const int*   dst_oo = (const int*)d_in[4];
    const int*   src_ho = (const int*)d_in[5];
    const int*   dst_ho = (const int*)d_in[6];
    const float* W_hh   = (const float*)d_in[7];
    const float* b_hh   = (const float*)d_in[8];
    const float* W_oo   = (const float*)d_in[9];
    const float* b_oo   = (const float*)d_in[10];
    const float* W_ho   = (const float*)d_in[11];
    const float* b_ho   = (const float*)d_in[12];
    const float* W_att  = (const float*)d_in[13];
    const float* b_att  = (const float*)d_in[14];
    const float* W_hn   = (const float*)d_in[15];
    const float* b_hn   = (const float*)d_in[16];
    const float* W_on   = (const float*)d_in[17];
    const float* b_on   = (const float*)d_in[18];
    float* out = (float*)d_out;

    void* p;
    __half *u_hh, *v_hh, *u_oo, *v_oo, *u_ho, *v_ho, *nfh, *z, *wt;
    int* deg;
    cudaGetSymbolAddress(&p, g_u_hh); u_hh = (__half*)p;
    cudaGetSymbolAddress(&p, g_v_hh); v_hh = (__half*)p;
    cudaGetSymbolAddress(&p, g_u_oo); u_oo = (__half*)p;
    cudaGetSymbolAddress(&p, g_v_oo); v_oo = (__half*)p;
    cudaGetSymbolAddress(&p, g_u_ho); u_ho = (__half*)p;
    cudaGetSymbolAddress(&p, g_v_ho); v_ho = (__half*)p;
    cudaGetSymbolAddress(&p, g_nfh);  nfh  = (__half*)p;
    cudaGetSymbolAddress(&p, g_z);    z    = (__half*)p;
    cudaGetSymbolAddress(&p, g_wt);   wt   = (__half*)p;
    cudaGetSymbolAddress(&p, g_deg);  deg  = (int*)p;

    cudaFuncSetAttribute(gemm_mma,
                         cudaFuncAttributeMaxDynamicSharedMemorySize, GEMM_SMEM);

    const size_t WOFF = (size_t)DD * DD;   // bottom half of [2D,D] weight
    const size_t MSZ  = (size_t)DD * DD;
    dim3 thr(256);

    // ---- fp16 operand prep + CSR bookkeeping ----
    cudaMemsetAsync(deg, 0, NN * sizeof(int));
    to_half_kernel<<<((NN * DD / 4) + 255) / 256, 256>>>(n_f, nfh, NN * DD / 4);
    {
        TP10 tp;
        tp.s[0] = W_hh;        tp.s[1] = W_hh + WOFF;
        tp.s[2] = W_ho;        tp.s[3] = W_hn;
        tp.s[4] = W_oo;        tp.s[5] = W_oo + WOFF;
        tp.s[6] = W_ho + WOFF; tp.s[7] = W_on;
        tp.s[8] = W_hn + WOFF; tp.s[9] = W_on + WOFF;
        transpose_half10_kernel<<<dim3(32, 32, 10), dim3(32, 8)>>>(tp, wt);
    }
    build_edges_hist_kernel<<<(E_TOT + 255) / 256, 256>>>(src_hh, dst_hh, src_oo, dst_oo, src_ho, dst_ho);
    scan_deg_kernel<<<1, 1024>>>();
    scatter_kernel<<<(E_TOT + 255) / 256, 256>>>();

    const __half* nfhH = nfh;
    const __half* nfhO = nfh + (size_t)NH * DD;
    float* outH = out;
    float* outO = out + (size_t)NH * DD;

    // merged first-phase GEMMs: all 8 outputs in one launch
    {
        Outs8 o;
        o.c[0] = u_hh; o.c[1] = v_hh; o.c[2] = u_ho; o.c[3] = outH;
        o.c[4] = u_oo; o.c[5] = v_oo; o.c[6] = v_ho; o.c[7] = outO;
        o.b[0] = nullptr; o.b[1] = b_hh; o.b[2] = nullptr; o.b[3] = nullptr;
        o.b[4] = nullptr; o.b[5] = b_oo; o.b[6] = b_ho;    o.b[7] = nullptr;
        o.f[0] = FLAG_HALF; o.f[1] = FLAG_HALF; o.f[2] = FLAG_HALF; o.f[3] = 0;
        o.f[4] = FLAG_HALF; o.f[5] = FLAG_HALF; o.f[6] = FLAG_HALF; o.f[7] = 0;
        gemm_mma<<<dim3(32, YH_TILES + YO_TILES), thr, GEMM_SMEM>>>(
            nfhH, nfhO, wt, wt + 4 * MSZ, o, NH, NO, YH_TILES);
    }

    // attention logits + softmax-weighted aggregation
    edge_logits_kernel<<<(E_TOT * 32 + 255) / 256, 256>>>(W_att, b_att);
    softmax_z_kernel<<<NN, 128>>>();

    // merged z-phase GEMMs: both node-update accumulations in one launch
    {
        Outs8 o;
        o.c[0] = outH; o.b[0] = b_hn; o.f[0] = FLAG_ACC | FLAG_RELU;
        o.c[4] = outO; o.b[4] = b_on; o.f[4] = FLAG_ACC | FLAG_RELU;
        o.c[1] = o.c[2] = o.c[3] = o.c[5] = o.c[6] = o.c[7] = nullptr;
        o.b[1] = o.b[2] = o.b[3] = o.b[5] = o.b[6] = o.b[7] = nullptr;
        o.f[1] = o.f[2] = o.f[3] = o.f[5] = o.f[6] = o.f[7] = 0;
        gemm_mma<<<dim3(8, YH_TILES + YO_TILES), thr, GEMM_SMEM>>>(
            z, z + (size_t)NH * DD, wt + 8 * MSZ, wt + 9 * MSZ, o, NH, NO, YH_TILES);
    }
}